// round 11
// baseline (speedup 1.0000x reference)
#include <cuda_runtime.h>

#define DMODEL     1024
#define NEXP       8
#define TOKENS_TOT 32768
#define TPB        128
#define WARPS      4                 // per CTA
#define TPW        16                // tokens per warp
#define TPG        4                 // tokens per inner group
#define NGRP       (TPW / TPG)       // 4
#define NCHUNK     (NGRP * 8)        // 32 flat chunk steps per warp
#define NBLOCKS    (TOKENS_TOT / (WARPS * TPW))   // 512

typedef unsigned long long ull;

// ---------- packed fp32x2 FMA (sm_103a) ----------
__device__ __forceinline__ ull ffma2(ull a, ull b, ull c) {
    ull d;
    asm("fma.rn.f32x2 %0, %1, %2, %3;" : "=l"(d) : "l"(a), "l"(b), "l"(c));
    return d;
}
__device__ __forceinline__ void unpack2(ull v, float& lo, float& hi) {
    asm("mov.b64 {%0, %1}, %2;" : "=f"(lo), "=f"(hi) : "l"(v));
}

// ---------- integer warp redux (f32 redux does NOT exist on sm_103) ----------
__device__ __forceinline__ unsigned redux_max_u32(unsigned v) {
    unsigned r;
    asm volatile("redux.sync.max.u32 %0, %1, 0xffffffff;" : "=r"(r) : "r"(v));
    return r;
}
__device__ __forceinline__ unsigned redux_min_u32(unsigned v) {
    unsigned r;
    asm volatile("redux.sync.min.u32 %0, %1, 0xffffffff;" : "=r"(r) : "r"(v));
    return r;
}

// Order-preserving float <-> u32 total-order map: u32 max == float max.
__device__ __forceinline__ unsigned fmono(float v) {
    unsigned u = __float_as_uint(v);
    return ((int)u < 0) ? ~u : (u ^ 0x80000000u);
}
__device__ __forceinline__ float fmono_inv(unsigned k) {
    return __uint_as_float(((int)k < 0) ? (k ^ 0x80000000u) : ~k);
}

// Warp-autonomous gating, depth-2 chunk prefetch. Lane owns dims
// {c*128 + lane*4 .. +4 | c=0..7}; a warp spans all 1024 dims of a token.
// W staged in SMEM (32 KB) once, re-read per chunk amortized over 4 tokens.
// x and W are loaded as ulonglong2 — the 16-byte loads ARE the packed f32x2
// operands, so there is zero packing-mov overhead.
__global__ void __launch_bounds__(TPB, 3)
gating_kernel(const float* __restrict__ x, const float* __restrict__ W,
              const float* __restrict__ b, float* __restrict__ out_w,
              float* __restrict__ out_i, int write_idx)
{
    __shared__ ulonglong2 Ws[NEXP * 256];   // 8 x 1024 floats = 32 KB

    const int tid  = threadIdx.x;
    const int lane = tid & 31;
    const int wid  = tid >> 5;

    // Stage W: 2048 x 16B / 128 threads = 16 each.
    {
        const ulonglong2* Wv = (const ulonglong2*)W;
#pragma unroll
        for (int i = 0; i < 16; i++)
            Ws[tid + i * TPB] = Wv[tid + i * TPB];
    }
    __syncthreads();   // the only block barrier in the kernel

    const int   elane = (lane >> 2) & 7;
    const float bval  = b[elane];

    const int t0 = (blockIdx.x * WARPS + wid) * TPW;
    // token row = 256 x 16B units; chunk c -> unit c*32 + lane
    const ulonglong2* xp = (const ulonglong2*)x + (size_t)t0 * 256 + lane;

    // flat chunk k (0..31): unit offset = (k>>3)*TPG*256 + (k&7)*32  (+ t*256)
    ulonglong2 xb[2][TPG];     // double buffer, depth-2 pipeline
#pragma unroll
    for (int t = 0; t < TPG; t++) {
        xb[0][t] = xp[0 * 32 + t * 256];   // chunk 0
        xb[1][t] = xp[1 * 32 + t * 256];   // chunk 1
    }

#pragma unroll 1
    for (int g = 0; g < NGRP; g++) {
        ull acc[NEXP][TPG];
#pragma unroll
        for (int e = 0; e < NEXP; e++)
#pragma unroll
            for (int t = 0; t < TPG; t++) acc[e][t] = 0ull;

#pragma unroll
        for (int c = 0; c < 8; c++) {
            // Consume buffer (parity c&1 since g*8 is even).
            ull xlo[TPG], xhi[TPG];
#pragma unroll
            for (int t = 0; t < TPG; t++) {
                xlo[t] = xb[c & 1][t].x;
                xhi[t] = xb[c & 1][t].y;
            }

            // Prefetch chunk k+2 into the buffer just consumed (clamped).
            {
                int kn = g * 8 + c + 2;
                kn = (kn < NCHUNK - 1) ? kn : (NCHUNK - 1);
                const int off = ((kn >> 3) * (TPG * 256)) + ((kn & 7) * 32);
#pragma unroll
                for (int t = 0; t < TPG; t++)
                    xb[c & 1][t] = xp[off + t * 256];
            }

            // W for this chunk, 4 experts at a time.
            const ulonglong2* wrow = Ws + c * 32 + lane;
#pragma unroll
            for (int eb = 0; eb < NEXP; eb += 4) {
                ulonglong2 w0 = wrow[(eb + 0) * 256];
                ulonglong2 w1 = wrow[(eb + 1) * 256];
                ulonglong2 w2 = wrow[(eb + 2) * 256];
                ulonglong2 w3 = wrow[(eb + 3) * 256];
#pragma unroll
                for (int t = 0; t < TPG; t++) {
                    acc[eb + 0][t] = ffma2(xhi[t], w0.y, ffma2(xlo[t], w0.x, acc[eb + 0][t]));
                    acc[eb + 1][t] = ffma2(xhi[t], w1.y, ffma2(xlo[t], w1.x, acc[eb + 1][t]));
                    acc[eb + 2][t] = ffma2(xhi[t], w2.y, ffma2(xlo[t], w2.x, acc[eb + 2][t]));
                    acc[eb + 3][t] = ffma2(xhi[t], w3.y, ffma2(xlo[t], w3.x, acc[eb + 3][t]));
                }
            }
        }

        // Finalize + epilogue per token, fully in-warp.
#pragma unroll
        for (int t = 0; t < TPG; t++) {
            float s[NEXP];
#pragma unroll
            for (int e = 0; e < NEXP; e++) {
                float lo, hi; unpack2(acc[e][t], lo, hi);
                s[e] = lo + hi;
            }

            // 9-shfl butterfly: experts over lane bits 4,3,2; dims over 1,0.
            const bool h16 = (lane & 16) != 0;
#pragma unroll
            for (int v = 0; v < 4; v++) {
                float d = __shfl_xor_sync(~0u, h16 ? s[v] : s[v + 4], 16);
                s[v] = (h16 ? s[v + 4] : s[v]) + d;
            }
            const bool h8 = (lane & 8) != 0;
#pragma unroll
            for (int v = 0; v < 2; v++) {
                float d = __shfl_xor_sync(~0u, h8 ? s[v] : s[v + 2], 8);
                s[v] = (h8 ? s[v + 2] : s[v]) + d;
            }
            const bool h4 = (lane & 4) != 0;
            {
                float d = __shfl_xor_sync(~0u, h4 ? s[0] : s[1], 4);
                s[0] = (h4 ? s[1] : s[0]) + d;
            }
            float r = s[0];
            r += __shfl_xor_sync(~0u, r, 2);
            r += __shfl_xor_sync(~0u, r, 1);

            // Lane holds the complete logit for expert `elane` (x4 copies).
            const float L = r + bval;
            const unsigned key = fmono(L);
            unsigned k1 = redux_max_u32(key);
            unsigned i1 = redux_min_u32((key == k1) ? (unsigned)elane : 0xFFu);
            unsigned key2 = ((unsigned)elane == i1) ? 0u : key;
            unsigned k2 = redux_max_u32(key2);
            unsigned i2 = redux_min_u32((key2 == k2) ? (unsigned)elane : 0xFFu);

            const float m1 = fmono_inv(k1);
            const float m2 = fmono_inv(k2);
            const float tt  = __expf(m2 - m1);     // m2 <= m1 -> (0,1]
            const float inv = 1.0f / (1.0f + tt);

            const int token = t0 + g * TPG + t;
            if ((lane & 3) == 0) {
                float wgt = ((unsigned)elane == i1) ? inv
                          : (((unsigned)elane == i2) ? tt * inv : 0.0f);
                out_w[token * 8 + elane] = wgt;
            }
            if (lane == t * 8 && write_idx)
                *(float2*)(out_i + token * 2) =
                    make_float2((float)i1, (float)i2);
        }
    }
}

extern "C" void kernel_launch(void* const* d_in, const int* in_sizes, int n_in,
                              void* d_out, int out_size)
{
    const float* x = nullptr; const float* W = nullptr; const float* b = nullptr;
    for (int i = 0; i < n_in; i++) {
        if (in_sizes[i] == NEXP)                b = (const float*)d_in[i];
        else if (in_sizes[i] == NEXP * DMODEL)  W = (const float*)d_in[i];
        else                                    x = (const float*)d_in[i];
    }

    float* ow = (float*)d_out;                       // weights: [B,S,E] f32
    float* oi = ow + (size_t)TOKENS_TOT * NEXP;      // indices (as f32): [B,S,2]
    const int need = TOKENS_TOT * NEXP + TOKENS_TOT * 2;
    const int write_idx = (out_size >= need) ? 1 : 0;

    gating_kernel<<<NBLOCKS, TPB>>>(x, W, b, ow, oi, write_idx);
}